// round 14
// baseline (speedup 1.0000x reference)
#include <cuda_runtime.h>
#include <cuda_bf16.h>
#include <stdint.h>
#include <math.h>

#define BATCHN 65536
#define QD 256

// ---- int8 activation buffers (2 limbs) + per-row scales ----
__device__ int8_t g_cq1[(long)BATCHN*QD],  g_cq2[(long)BATCHN*QD];   // cur
__device__ int8_t g_hq1[(long)BATCHN*768], g_hq2[(long)BATCHN*768]; // hidden (768 or 512)
__device__ int8_t g_tq1[(long)BATCHN*QD],  g_tq2[(long)BATCHN*QD];  // tmp
__device__ int8_t g_xq1[(long)BATCHN*QD],  g_xq2[(long)BATCHN*QD];  // c2 / nl-mid
__device__ float  g_cs[BATCHN], g_hs[BATCHN], g_ts[BATCHN], g_xs[BATCHN];
// fp32 intermediates
__device__ float g_h32 [(long)BATCHN*768];
__device__ float g_tmp32[(long)BATCHN*QD];
__device__ float g_c232 [(long)BATCHN*QD];
__device__ float g_nl32 [(long)BATCHN*QD];
// weights: 2 limbs + per-n scales
__device__ int8_t g_wq1[3145728], g_wq2[3145728];
__device__ float  g_ws[10240];
__device__ float  g_wf[2*256*256];
__device__ float  g_battn[2*256];
__device__ float  g_lin[8*256];

__device__ __forceinline__ unsigned cvsm(const void* p){
    unsigned a;
    asm("{ .reg .u64 t; cvta.to.shared.u64 t, %1; cvt.u32.u64 %0, t; }" : "=r"(a) : "l"(p));
    return a;
}
__device__ __forceinline__ void ldm4(unsigned a, unsigned& r0, unsigned& r1, unsigned& r2, unsigned& r3){
    asm volatile("ldmatrix.sync.aligned.m8n8.x4.shared.b16 {%0,%1,%2,%3}, [%4];"
                 : "=r"(r0),"=r"(r1),"=r"(r2),"=r"(r3) : "r"(a));
}
__device__ __forceinline__ void immas8(int* c, const unsigned* a, const unsigned* b){
    asm volatile("mma.sync.aligned.m16n8k32.row.col.s32.s8.s8.s32 "
                 "{%0,%1,%2,%3},{%4,%5,%6,%7},{%8,%9},{%0,%1,%2,%3};"
                 : "+r"(c[0]),"+r"(c[1]),"+r"(c[2]),"+r"(c[3])
                 : "r"(a[0]),"r"(a[1]),"r"(a[2]),"r"(a[3]),"r"(b[0]),"r"(b[1]));
}
#define QMAXF 16128.0f
__device__ __forceinline__ void quant2(float v, float inv, int8_t& a1, int8_t& a2){
    int q = __float2int_rn(v*inv);
    int h = (q+64)>>7;
    a1=(int8_t)h; a2=(int8_t)(q-(h<<7));
}
__device__ __forceinline__ float wredmax(float m){
#pragma unroll
    for(int o=16;o;o>>=1) m=fmaxf(m,__shfl_xor_sync(0xffffffffu,m,o));
    return m;
}

// ---- int8 GEMM: C32[M,N] = epi(As[m]*Ws[n]*(16384*acc1+128*acc2) + bias) ----
#define LDTB 80                    // bytes/row in smem (conflict-free for ldmatrix)
#define ASZB (128*LDTB)            // 10240
#define STGB (4*ASZB)              // 40960
#define SM_TOT (2*STGB)            // 81920

__device__ __forceinline__ void ldg_q(uint4* p,
    const int8_t* __restrict__ A1, const int8_t* __restrict__ A2,
    const int8_t* __restrict__ B1, const int8_t* __restrict__ B2,
    long rowBase, int colBase, int K, int k0, int tid)
{
    int r=tid>>2, cb=(tid&3)<<4;
    long ga=(rowBase+r)*(long)K + k0 + cb;
    long gb=((long)(colBase+r))*(long)K + k0 + cb;
    p[0]=*(const uint4*)(A1+ga); p[1]=*(const uint4*)(A2+ga);
    p[2]=*(const uint4*)(B1+gb); p[3]=*(const uint4*)(B2+gb);
}
__device__ __forceinline__ void sts_q(char* st, const uint4* p, int tid){
    int r=tid>>2, cb=(tid&3)<<4;
    int so=r*LDTB+cb;
    *(uint4*)(st+so)        = p[0];
    *(uint4*)(st+ASZB+so)   = p[1];
    *(uint4*)(st+2*ASZB+so) = p[2];
    *(uint4*)(st+3*ASZB+so) = p[3];
}

// EPI: 0 bias, 1 silu, 2 tanh, 3 fused gate/combine (reads tmpP fp32)
template<int EPI>
__global__ void __launch_bounds__(512,1) gemm_q(
    const int8_t* __restrict__ A1, const int8_t* __restrict__ A2, const float* __restrict__ As,
    const int8_t* __restrict__ B1, const int8_t* __restrict__ B2, const float* __restrict__ Ws,
    const float* __restrict__ bias, float* __restrict__ C32,
    const float* __restrict__ tmpP, const float* __restrict__ gpP, const float* __restrict__ linP,
    int K, int N)
{
    extern __shared__ char sm[];
    const int tid=threadIdx.x, lane=tid&31, warp=tid>>5;
    const int wm=warp>>2, wn=warp&3;      // 4x4 warps, 32x32 tiles
    const long rowBase=(long)blockIdx.y*128;
    const int  colBase=blockIdx.x*128;

    int acc1[2][4][4], acc2[2][4][4];
#pragma unroll
    for(int a=0;a<2;a++)
#pragma unroll
    for(int b=0;b<4;b++)
#pragma unroll
    for(int c=0;c<4;c++){ acc1[a][b][c]=0; acc2[a][b][c]=0; }

    const int nIter=K>>6;
    uint4 pref[4];
    ldg_q(pref, A1,A2,B1,B2, rowBase,colBase, K, 0, tid);
    sts_q(sm, pref, tid);
    __syncthreads();

    for(int i=0;i<nIter;i++){
        if(i+1<nIter)
            ldg_q(pref, A1,A2,B1,B2, rowBase,colBase, K, (i+1)*64, tid);
        char* cur = sm + (i&1)*STGB;
        char* sA1=cur; char* sA2=cur+ASZB; char* sB1=cur+2*ASZB; char* sB2=cur+3*ASZB;
#pragma unroll
        for(int kb=0;kb<2;kb++){
            const int colo = kb*32 + ((lane>>4)<<4);
            unsigned a1f[2][4], a2f[2][4], b1f[4][2], b2f[4][2];
#pragma unroll
            for(int mt=0;mt<2;mt++){
                int row=wm*32+mt*16+(lane&15);
                ldm4(cvsm(sA1+row*LDTB+colo), a1f[mt][0],a1f[mt][1],a1f[mt][2],a1f[mt][3]);
                ldm4(cvsm(sA2+row*LDTB+colo), a2f[mt][0],a2f[mt][1],a2f[mt][2],a2f[mt][3]);
            }
#pragma unroll
            for(int np=0;np<2;np++){
                int row=wn*32+np*16+(lane&15);
                unsigned t0,t1,t2,t3;
                ldm4(cvsm(sB1+row*LDTB+colo), t0,t1,t2,t3);
                b1f[2*np][0]=t0; b1f[2*np][1]=t2; b1f[2*np+1][0]=t1; b1f[2*np+1][1]=t3;
                ldm4(cvsm(sB2+row*LDTB+colo), t0,t1,t2,t3);
                b2f[2*np][0]=t0; b2f[2*np][1]=t2; b2f[2*np+1][0]=t1; b2f[2*np+1][1]=t3;
            }
#pragma unroll
            for(int mt=0;mt<2;mt++)
#pragma unroll
            for(int nt=0;nt<4;nt++){
                immas8(acc1[mt][nt], a1f[mt], b1f[nt]);
                immas8(acc2[mt][nt], a1f[mt], b2f[nt]);
                immas8(acc2[mt][nt], a2f[mt], b1f[nt]);
            }
        }
        if(i+1<nIter){
            sts_q(sm+((i+1)&1)*STGB, pref, tid);
            __syncthreads();
        }
    }

#pragma unroll
    for(int mt=0;mt<2;mt++)
#pragma unroll
    for(int nt=0;nt<4;nt++){
        int n0=colBase+wn*32+nt*8+((lane&3)<<1);
        float w0=Ws[n0], w1=Ws[n0+1];
        float b0=0.f,b1=0.f;
        if(EPI!=3 && bias){ b0=bias[n0]; b1=bias[n0+1]; }
        float l0=0,p30=0,p40=0,p50=0,l1=0,p31=0,p41=0,p51=0;
        if(EPI==3){
            l0=linP[n0]; p30=gpP[n0*6+3]; p40=gpP[n0*6+4]; p50=gpP[n0*6+5];
            l1=linP[n0+1]; p31=gpP[(n0+1)*6+3]; p41=gpP[(n0+1)*6+4]; p51=gpP[(n0+1)*6+5];
        }
#pragma unroll
        for(int hh=0;hh<2;hh++){
            long row=rowBase+wm*32+mt*16+(lane>>2)+hh*8;
            float sA=As[row];
            long o=row*(long)N+n0;
            float v0=sA*w0*(16384.f*(float)acc1[mt][nt][2*hh]  +128.f*(float)acc2[mt][nt][2*hh])  +b0;
            float v1=sA*w1*(16384.f*(float)acc1[mt][nt][2*hh+1]+128.f*(float)acc2[mt][nt][2*hh+1])+b1;
            if(EPI==1){ v0*=1.f/(1.f+__expf(-v0)); v1*=1.f/(1.f+__expf(-v1)); }
            if(EPI==2){ v0=tanhf(v0); v1=tanhf(v1); }
            if(EPI==3){
                float t0v=tmpP[o], t1v=tmpP[o+1];
                float g0=(l0*t0v + 0.5f*sinf(p30*t0v+p40) + 0.5f*cosf(p50*t0v))*0.25f;
                float g1=(l1*t1v + 0.5f*sinf(p31*t1v+p41) + 0.5f*cosf(p51*t1v))*0.25f;
                v0=(t0v + 0.3f*g0 + 0.2f*v0)*(1.0f/1.5f);
                v1=(t1v + 0.3f*g1 + 0.2f*v1)*(1.0f/1.5f);
            }
            float2 f; f.x=v0; f.y=v1; *(float2*)(C32+o)=f;
        }
    }
}

// ---- elementwise / quantize kernels (warp per row) ----
__global__ void k_quant(const float* __restrict__ src, int8_t* __restrict__ q1, int8_t* __restrict__ q2,
                        float* __restrict__ scl, int W){
    int row=blockIdx.x*8+(threadIdx.x>>5);
    int lane=threadIdx.x&31;
    const float* r=src+(long)row*W;
    int nv=W>>5;
    float v[16]; float m=0.f;
    for(int j=0;j<nv;j++){ v[j]=r[lane+32*j]; m=fmaxf(m,fabsf(v[j])); }
    m=wredmax(m);
    float inv=(m>0.f)?QMAXF/m:0.f;
    if(lane==0) scl[row]=m/QMAXF;
    long base=(long)row*W;
    for(int j=0;j<nv;j++){
        int8_t a,b; quant2(v[j],inv,a,b);
        q1[base+lane+32*j]=a; q2[base+lane+32*j]=b;
    }
}

__global__ void k_init(const float* __restrict__ x, int8_t* __restrict__ q1, int8_t* __restrict__ q2,
                       float* __restrict__ scl){
    int row=blockIdx.x*8+(threadIdx.x>>5);
    int lane=threadIdx.x&31;
    const float* r=x+(long)row*QD;
    float v[8]; float m=0.f;
#pragma unroll
    for(int j=0;j<8;j++){ v[j]=r[lane+32*j]; m=fmaxf(m,fabsf(v[j])); }
    m=wredmax(m);
    float inv=(m>0.f)?QMAXF/m:0.f;
    if(lane==0) scl[row]=m/QMAXF;
    long base=(long)row*QD;
#pragma unroll
    for(int j=0;j<8;j++){
        int8_t a,b; quant2(v[j],inv,a,b);
        q1[base+lane+32*j]=a; q2[base+lane+32*j]=b;
    }
}

__global__ void k_ln_gelu(const float* __restrict__ h, const float* __restrict__ w, const float* __restrict__ b,
                          int8_t* __restrict__ q1, int8_t* __restrict__ q2, float* __restrict__ scl){
    int row=blockIdx.x*8+(threadIdx.x>>5);
    int lane=threadIdx.x&31;
    const float* hr=h+(long)row*768;
    float v[24]; float s=0.f,s2=0.f;
#pragma unroll
    for(int j=0;j<24;j++){ float x=hr[lane+32*j]; v[j]=x; s+=x; s2+=x*x; }
#pragma unroll
    for(int o=16;o;o>>=1){ s+=__shfl_xor_sync(0xffffffffu,s,o); s2+=__shfl_xor_sync(0xffffffffu,s2,o); }
    float mu=s*(1.f/768.f);
    float var=s2*(1.f/768.f)-mu*mu;
    float inv=rsqrtf(var+1e-5f);
    float m=0.f;
#pragma unroll
    for(int j=0;j<24;j++){
        int q=lane+32*j;
        float y=(v[j]-mu)*inv*w[q]+b[q];
        float g=0.5f*y*(1.f+erff(y*0.70710678118654752f));
        v[j]=g; m=fmaxf(m,fabsf(g));
    }
    m=wredmax(m);
    float qi=(m>0.f)?QMAXF/m:0.f;
    if(lane==0) scl[row]=m/QMAXF;
    long base=(long)row*768;
#pragma unroll
    for(int j=0;j<24;j++){
        int8_t a,bq; quant2(v[j],qi,a,bq);
        q1[base+lane+32*j]=a; q2[base+lane+32*j]=bq;
    }
}

__global__ void k_final(const float* __restrict__ c2, const float* __restrict__ nl,
                        int8_t* __restrict__ q1, int8_t* __restrict__ q2, float* __restrict__ cs,
                        float* __restrict__ outp, float alpha){
    int row=blockIdx.x*8+(threadIdx.x>>5);
    int lane=threadIdx.x&31;
    long base=(long)row*QD;
    float rs=cs[row];
    float v[8]; float ss=0.f;
#pragma unroll
    for(int j=0;j<8;j++){
        int q=lane+32*j;
        float x=c2[base+q];
        if(nl) x+=0.1f*nl[base+q];
        float res=rs*(128.f*(float)q1[base+q]+(float)q2[base+q]);
        float y=alpha*x+(1.f-alpha)*res;
        v[j]=y; ss+=y*y;
    }
#pragma unroll
    for(int o=16;o;o>>=1) ss+=__shfl_xor_sync(0xffffffffu,ss,o);
    float inv=1.f/(sqrtf(ss)+1e-8f);
    float m=0.f;
#pragma unroll
    for(int j=0;j<8;j++){ v[j]=tanhf(v[j]*inv); m=fmaxf(m,fabsf(v[j])); }
    if(outp){
#pragma unroll
        for(int j=0;j<8;j++) outp[base+lane+32*j]=v[j];
    } else {
        m=wredmax(m);
        float qi=(m>0.f)?QMAXF/m:0.f;
        if(lane==0) cs[row]=m/QMAXF;
#pragma unroll
        for(int j=0;j<8;j++){
            int8_t a,b; quant2(v[j],qi,a,b);
            q1[base+lane+32*j]=a; q2[base+lane+32*j]=b;
        }
    }
}

// ---- weight quantization (warp per n-row, transposed [N][K]) ----
__device__ __forceinline__ void wq_row(const float* src, int K, int N, int n, int lane, int do_tanh,
                                       int8_t* q1, int8_t* q2, float* wsp){
    float v[24]; int nv=K>>5; float m=0.f;
    for(int j=0;j<nv;j++){
        float x=src[(long)(lane+32*j)*N+n];
        if(do_tanh) x=tanhf(x);
        v[j]=x; m=fmaxf(m,fabsf(x));
    }
    m=wredmax(m);
    float qi=(m>0.f)?QMAXF/m:0.f;
    if(lane==0) wsp[n]=m/QMAXF;
    for(int j=0;j<nv;j++){
        int8_t a,b; quant2(v[j],qi,a,b);
        q1[(long)n*K+lane+32*j]=a; q2[(long)n*K+lane+32*j]=b;
    }
}

__global__ void k_wsplit_big(const float* __restrict__ d0w1, const float* __restrict__ d0w2,
                             const float* __restrict__ d1w1, const float* __restrict__ d1w2,
                             int8_t* __restrict__ wq1, int8_t* __restrict__ wq2, float* __restrict__ ws){
    int y=blockIdx.y;
    int n=blockIdx.x*8+(threadIdx.x>>5);
    int lane=threadIdx.x&31;
    const float* src; long qo; int so,K,N;
    if(y<3){      int i=y;   src=d0w1+(long)i*196608; K=256;N=768; qo=0       +(long)i*196608; so=0   +i*768; }
    else if(y<6){ int i=y-3; src=d0w2+(long)i*196608; K=768;N=256; qo=589824 +(long)i*196608; so=2304+i*256; }
    else if(y<9){ int i=y-6; src=d1w1+(long)i*131072; K=256;N=512; qo=1179648+(long)i*131072; so=3072+i*512; }
    else {        int i=y-9; src=d1w2+(long)i*131072; K=512;N=256; qo=1572864+(long)i*131072; so=4608+i*256; }
    if(n>=N) return;
    wq_row(src,K,N,n,lane,0, wq1+qo,wq2+qo, ws+so);
}

__global__ void k_wsplit_small(const float* __restrict__ wf, const float* __restrict__ ent,
                               const float* __restrict__ nw1, const float* __restrict__ nw2,
                               int8_t* __restrict__ wq1, int8_t* __restrict__ wq2, float* __restrict__ ws){
    int y=blockIdx.y;
    int n=blockIdx.x*8+(threadIdx.x>>5);
    int lane=threadIdx.x&31;
    const float* src; long qo; int so; int th=0;
    if(y<2){       src=wf +(long)y*65536;      qo=1966080+(long)y*65536;      so=5376+y*256; }
    else if(y<10){ src=ent+(long)(y-2)*65536;  qo=2097152+(long)(y-2)*65536;  so=5888+(y-2)*256; th=1; }
    else if(y<14){ src=nw1+(long)(y-10)*65536; qo=2621440+(long)(y-10)*65536; so=7936+(y-10)*256; }
    else {         src=nw2+(long)(y-14)*65536; qo=2883584+(long)(y-14)*65536; so=8960+(y-14)*256; }
    wq_row(src,256,256,n,lane,th, wq1+qo,wq2+qo, ws+so);
}

__global__ void k_attn_fuse(const float* __restrict__ wqkv, const float* __restrict__ bqkv,
                            const float* __restrict__ wo, const float* __restrict__ bo,
                            float* __restrict__ wf, float* __restrict__ battn){
    int i=blockIdx.y;
    int idx=blockIdx.x*256+threadIdx.x;
    int k=idx>>8, n=idx&255;
    const float* Wv=wqkv+(long)i*256*768+512;
    const float* Wo=wo+(long)i*256*256;
    float s=0.f;
    for(int j=0;j<256;j++) s+=Wv[(long)k*768+j]*Wo[(long)j*256+n];
    wf[(long)i*65536+idx]=s;
    if(k==0){
        float sb=bo[i*256+n];
        for(int j=0;j<256;j++) sb+=bqkv[(long)i*768+512+j]*Wo[(long)j*256+n];
        battn[i*256+n]=sb;
    }
}

__global__ void k_lin(const float* __restrict__ gp, float* __restrict__ lin){
    int idx=blockIdx.x*256+threadIdx.x;
    const float* p=gp+(long)idx*6;
    lin[idx]=sinf(p[0])+cosf(p[1])+tanhf(p[2]);
}

static void* symaddr(const void* s){ void* p=nullptr; cudaGetSymbolAddress(&p, s); return p; }

static void gemmq(int epi, const int8_t* A1,const int8_t* A2,const float* As,
                  const int8_t* B1,const int8_t* B2,const float* Ws,
                  const float* bias, float* C32,
                  const float* tmpP, const float* gpP, const float* linP, int K,int N){
    dim3 grid(N/128, BATCHN/128);
    if(epi==0)      gemm_q<0><<<grid,512,SM_TOT>>>(A1,A2,As,B1,B2,Ws,bias,C32,tmpP,gpP,linP,K,N);
    else if(epi==1) gemm_q<1><<<grid,512,SM_TOT>>>(A1,A2,As,B1,B2,Ws,bias,C32,tmpP,gpP,linP,K,N);
    else if(epi==2) gemm_q<2><<<grid,512,SM_TOT>>>(A1,A2,As,B1,B2,Ws,bias,C32,tmpP,gpP,linP,K,N);
    else            gemm_q<3><<<grid,512,SM_TOT>>>(A1,A2,As,B1,B2,Ws,bias,C32,tmpP,gpP,linP,K,N);
}

extern "C" void kernel_launch(void* const* d_in, const int* in_sizes, int n_in,
                              void* d_out, int out_size){
    (void)in_sizes;(void)n_in;(void)out_size;
    cudaFuncSetAttribute(gemm_q<0>, cudaFuncAttributeMaxDynamicSharedMemorySize, SM_TOT);
    cudaFuncSetAttribute(gemm_q<1>, cudaFuncAttributeMaxDynamicSharedMemorySize, SM_TOT);
    cudaFuncSetAttribute(gemm_q<2>, cudaFuncAttributeMaxDynamicSharedMemorySize, SM_TOT);
    cudaFuncSetAttribute(gemm_q<3>, cudaFuncAttributeMaxDynamicSharedMemorySize, SM_TOT);

    const float* x   =(const float*)d_in[0];
    const float* d0w1=(const float*)d_in[1];
    const float* d0b1=(const float*)d_in[2];
    const float* lnw =(const float*)d_in[3];
    const float* lnb =(const float*)d_in[4];
    const float* d0w2=(const float*)d_in[5];
    const float* d0b2=(const float*)d_in[6];
    const float* d1w1=(const float*)d_in[7];
    const float* d1b1=(const float*)d_in[8];
    const float* d1w2=(const float*)d_in[9];
    const float* d1b2=(const float*)d_in[10];
    const float* wqkv=(const float*)d_in[11];
    const float* bqkv=(const float*)d_in[12];
    const float* wo  =(const float*)d_in[13];
    const float* bo  =(const float*)d_in[14];
    const float* gp  =(const float*)d_in[15];
    const float* ent =(const float*)d_in[16];
    const float* nw1 =(const float*)d_in[17];
    const float* nb1 =(const float*)d_in[18];
    const float* nw2 =(const float*)d_in[19];
    const float* nb2 =(const float*)d_in[20];

    int8_t* cq1=(int8_t*)symaddr(g_cq1); int8_t* cq2=(int8_t*)symaddr(g_cq2);
    int8_t* hq1=(int8_t*)symaddr(g_hq1); int8_t* hq2=(int8_t*)symaddr(g_hq2);
    int8_t* tq1=(int8_t*)symaddr(g_tq1); int8_t* tq2=(int8_t*)symaddr(g_tq2);
    int8_t* xq1=(int8_t*)symaddr(g_xq1); int8_t* xq2=(int8_t*)symaddr(g_xq2);
    float* cs=(float*)symaddr(g_cs); float* hs=(float*)symaddr(g_hs);
    float* ts=(float*)symaddr(g_ts); float* xs=(float*)symaddr(g_xs);
    float* h32  =(float*)symaddr(g_h32);
    float* tmp32=(float*)symaddr(g_tmp32);
    float* c232 =(float*)symaddr(g_c232);
    float* nl32 =(float*)symaddr(g_nl32);
    int8_t* wq1=(int8_t*)symaddr(g_wq1); int8_t* wq2=(int8_t*)symaddr(g_wq2);
    float* ws  =(float*)symaddr(g_ws);
    float* wf   =(float*)symaddr(g_wf);
    float* battn=(float*)symaddr(g_battn);
    float* lin  =(float*)symaddr(g_lin);

    const long O_D0W1=0, O_D0W2=589824, O_D1W1=1179648, O_D1W2=1572864;
    const long O_ATT=1966080, O_TENT=2097152, O_NW1=2621440, O_NW2=2883584;
    const int  S_D0W1=0, S_D0W2=2304, S_D1W1=3072, S_D1W2=4608;
    const int  S_ATT=5376, S_TENT=5888, S_NW1=7936, S_NW2=8960;

    const int QROWB = BATCHN/8;   // warp-per-row blocks

    // launches 1-3 prep; #4 = first GEMM (ncu target)
    k_wsplit_big<<<dim3(96,12),256>>>(d0w1,d0w2,d1w1,d1w2, wq1,wq2,ws);
    k_init<<<QROWB,256>>>(x, cq1,cq2, cs);
    k_attn_fuse<<<dim3(256,2),256>>>(wqkv,bqkv,wo,bo,wf,battn);

    for(int li=0;li<8;li++){
        int t=li%3;
        if(t==0){
            int i=li/3;
            gemmq(0, cq1,cq2,cs, wq1+O_D0W1+(long)i*196608, wq2+O_D0W1+(long)i*196608, ws+S_D0W1+i*768,
                  d0b1+(long)i*768, h32, nullptr,nullptr,nullptr, 256,768);
            if(li==0){
                k_wsplit_small<<<dim3(32,18),256>>>(wf,ent,nw1,nw2, wq1,wq2,ws);
                k_lin<<<8,256>>>(gp, lin);
            }
            k_ln_gelu<<<QROWB,256>>>(h32, lnw+(long)i*768, lnb+(long)i*768, hq1,hq2,hs);
            gemmq(0, hq1,hq2,hs, wq1+O_D0W2+(long)i*196608, wq2+O_D0W2+(long)i*196608, ws+S_D0W2+i*256,
                  d0b2+(long)i*256, tmp32, nullptr,nullptr,nullptr, 768,256);
        } else if(t==1){
            int i=(li-1)/3;
            gemmq(1, cq1,cq2,cs, wq1+O_D1W1+(long)i*131072, wq2+O_D1W1+(long)i*131072, ws+S_D1W1+i*512,
                  d1b1+(long)i*512, h32, nullptr,nullptr,nullptr, 256,512);
            k_quant<<<QROWB,256>>>(h32, hq1,hq2,hs, 512);
            gemmq(0, hq1,hq2,hs, wq1+O_D1W2+(long)i*131072, wq2+O_D1W2+(long)i*131072, ws+S_D1W2+i*256,
                  d1b2+(long)i*256, tmp32, nullptr,nullptr,nullptr, 512,256);
        } else {
            int i=(li-2)/3;
            gemmq(0, cq1,cq2,cs, wq1+O_ATT+(long)i*65536, wq2+O_ATT+(long)i*65536, ws+S_ATT+i*256,
                  battn+(long)i*256, tmp32, nullptr,nullptr,nullptr, 256,256);
        }
        // quantize tmp, entangle GEMM with fused gate/combine epilogue -> c2 fp32
        k_quant<<<QROWB,256>>>(tmp32, tq1,tq2,ts, 256);
        gemmq(3, tq1,tq2,ts, wq1+O_TENT+(long)li*65536, wq2+O_TENT+(long)li*65536, ws+S_TENT+li*256,
              nullptr, c232, tmp32, gp+(long)li*256*6, lin+(long)li*256, 256,256);

        const float* nlptr=nullptr;
        if(li&1){
            int j=li/2;
            k_quant<<<QROWB,256>>>(c232, xq1,xq2,xs, 256);
            gemmq(2, xq1,xq2,xs, wq1+O_NW1+(long)j*65536, wq2+O_NW1+(long)j*65536, ws+S_NW1+j*256,
                  nb1+(long)j*256, h32, nullptr,nullptr,nullptr, 256,256);
            k_quant<<<QROWB,256>>>(h32, xq1,xq2,xs, 256);
            gemmq(0, xq1,xq2,xs, wq1+O_NW2+(long)j*65536, wq2+O_NW2+(long)j*65536, ws+S_NW2+j*256,
                  nb2+(long)j*256, nl32, nullptr,nullptr,nullptr, 256,256);
            nlptr=nl32;
        }
        float alpha=(li<4)?0.8f:0.6f;
        float* outp=(li==7)?(float*)d_out:nullptr;
        k_final<<<QROWB,256>>>(c232, nlptr, cq1,cq2,cs, outp, alpha);
    }
}

// round 15
// speedup vs baseline: 1.9033x; 1.9033x over previous
#include <cuda_runtime.h>
#include <cuda_fp16.h>
#include <stdint.h>
#include <math.h>

typedef __half fp16;
#define BATCHN 65536
#define QD 256

__device__ float g_h32 [(long)BATCHN*768];
__device__ float g_nl32[(long)BATCHN*QD];
__device__ fp16  g_curh[(long)BATCHN*QD],  g_curl[(long)BATCHN*QD];
__device__ fp16  g_hh  [(long)BATCHN*768], g_hl  [(long)BATCHN*768];
__device__ fp16  g_tmph[(long)BATCHN*QD],  g_tmpl[(long)BATCHN*QD];
__device__ fp16  g_c2h [(long)BATCHN*QD],  g_c2l [(long)BATCHN*QD];
__device__ fp16  g_w_h[3145728], g_w_l[3145728];
__device__ float g_wf[2*256*256];
__device__ float g_battn[2*256];
__device__ float g_lin[8*256];

__device__ __forceinline__ void split2(float v, fp16& h, fp16& l){
    h = __float2half(v);
    l = __float2half(v - __half2float(h));
}
__device__ __forceinline__ unsigned cvsm(const void* p){
    unsigned a;
    asm("{ .reg .u64 t; cvta.to.shared.u64 t, %1; cvt.u32.u64 %0, t; }" : "=r"(a) : "l"(p));
    return a;
}
__device__ __forceinline__ void ldm4(unsigned a, unsigned& r0, unsigned& r1, unsigned& r2, unsigned& r3){
    asm volatile("ldmatrix.sync.aligned.m8n8.x4.shared.b16 {%0,%1,%2,%3}, [%4];"
                 : "=r"(r0),"=r"(r1),"=r"(r2),"=r"(r3) : "r"(a));
}
// f32-accumulate fp16 MMA (hh product)
__device__ __forceinline__ void mmaf32(float* c, const unsigned* a, const unsigned* b){
    asm volatile("mma.sync.aligned.m16n8k16.row.col.f32.f16.f16.f32 "
                 "{%0,%1,%2,%3},{%4,%5,%6,%7},{%8,%9},{%0,%1,%2,%3};"
                 : "+f"(c[0]),"+f"(c[1]),"+f"(c[2]),"+f"(c[3])
                 : "r"(a[0]),"r"(a[1]),"r"(a[2]),"r"(a[3]),"r"(b[0]),"r"(b[1]));
}
// f16-accumulate fp16 MMA (cross products; potentially double rate)
__device__ __forceinline__ void mmaf16(unsigned* c, const unsigned* a, const unsigned* b){
    asm volatile("mma.sync.aligned.m16n8k16.row.col.f16.f16.f16.f16 "
                 "{%0,%1},{%2,%3,%4,%5},{%6,%7},{%0,%1};"
                 : "+r"(c[0]),"+r"(c[1])
                 : "r"(a[0]),"r"(a[1]),"r"(a[2]),"r"(a[3]),"r"(b[0]),"r"(b[1]));
}

#define BM 128
#define BN 128
#define BKK 32
#define LDT 40                 // fp16; 80B rows, ldmatrix conflict-free
#define ASZ (BM*LDT)           // 5120 fp16 per array
#define STG (4*ASZ)
#define SM_TOT (2*STG*2)       // 81920 bytes

__device__ __forceinline__ void ldg_stage(uint4* p,
    const fp16* __restrict__ Ah, const fp16* __restrict__ Al,
    const fp16* __restrict__ Bh, const fp16* __restrict__ Bl,
    long rowBase, int colBase, int K, int k0, int tid)
{
    int r=tid>>2, kc0=(tid&3)<<3;
    long ga=(rowBase+r)*(long)K + k0 + kc0;
    long gb=((long)(colBase+r))*(long)K + k0 + kc0;
    p[0]=*(const uint4*)(Ah+ga); p[1]=*(const uint4*)(Al+ga);
    p[2]=*(const uint4*)(Bh+gb); p[3]=*(const uint4*)(Bl+gb);
}
__device__ __forceinline__ void sts_stage(fp16* st, const uint4* p, int tid){
    int r=tid>>2, kc0=(tid&3)<<3;
    int so=r*LDT+kc0;
    *(uint4*)(st+so)       = p[0];
    *(uint4*)(st+ASZ+so)   = p[1];
    *(uint4*)(st+2*ASZ+so) = p[2];
    *(uint4*)(st+3*ASZ+so) = p[3];
}

// C[M,N] = epi(A@W + bias). A hi/lo [M][K]; W transposed hi/lo [N][K].
// EPI: 0 none, 1 silu, 2 tanh, 3 fused-combine.
template<int EPI>
__global__ void __launch_bounds__(512,1) gemm_k(
    const fp16* __restrict__ Ah, const fp16* __restrict__ Al,
    const fp16* __restrict__ Bh, const fp16* __restrict__ Bl,
    const float* __restrict__ bias,
    float* __restrict__ C32, fp16* __restrict__ Ch, fp16* __restrict__ Cl,
    const fp16* __restrict__ tmphP, const fp16* __restrict__ tmplP,
    const float* __restrict__ gpP, const float* __restrict__ linP,
    int K, int N)
{
    extern __shared__ fp16 sm[];
    const int tid=threadIdx.x, lane=tid&31, warp=tid>>5;
    const int wm=warp>>2, wn=warp&3;      // 4x4 warp grid, 32x32 warp tiles
    const long rowBase=(long)blockIdx.y*BM;
    const int  colBase=blockIdx.x*BN;

    float    accF[2][4][4];
    unsigned accH[2][4][2];
#pragma unroll
    for(int a=0;a<2;a++)
#pragma unroll
    for(int b=0;b<4;b++){
#pragma unroll
        for(int c=0;c<4;c++) accF[a][b][c]=0.f;
        accH[a][b][0]=0u; accH[a][b][1]=0u;
    }

    const int nIter=K/BKK;
    uint4 pref[4];
    ldg_stage(pref, Ah,Al,Bh,Bl, rowBase,colBase, K, 0, tid);
    sts_stage(sm, pref, tid);
    __syncthreads();

    for(int i=0;i<nIter;i++){
        if(i+1<nIter)
            ldg_stage(pref, Ah,Al,Bh,Bl, rowBase,colBase, K, (i+1)*BKK, tid);
        fp16* cur = sm + (i&1)*STG;
        fp16* sAh=cur; fp16* sAl=cur+ASZ; fp16* sBh=cur+2*ASZ; fp16* sBl=cur+3*ASZ;
#pragma unroll
        for(int ks=0;ks<2;ks++){
            unsigned aH[2][4], aL[2][4], bH[4][2], bL[4][2];
            const int colo = ks*16 + ((lane>>4)<<3);
#pragma unroll
            for(int mt=0;mt<2;mt++){
                int row=wm*32+mt*16+(lane&15);
                ldm4(cvsm(sAh+row*LDT+colo), aH[mt][0],aH[mt][1],aH[mt][2],aH[mt][3]);
                ldm4(cvsm(sAl+row*LDT+colo), aL[mt][0],aL[mt][1],aL[mt][2],aL[mt][3]);
            }
#pragma unroll
            for(int np=0;np<2;np++){
                int row=wn*32+np*16+(lane&15);
                unsigned t0,t1,t2,t3;
                ldm4(cvsm(sBh+row*LDT+colo), t0,t1,t2,t3);
                bH[2*np][0]=t0; bH[2*np][1]=t2; bH[2*np+1][0]=t1; bH[2*np+1][1]=t3;
                ldm4(cvsm(sBl+row*LDT+colo), t0,t1,t2,t3);
                bL[2*np][0]=t0; bL[2*np][1]=t2; bL[2*np+1][0]=t1; bL[2*np+1][1]=t3;
            }
#pragma unroll
            for(int mt=0;mt<2;mt++)
#pragma unroll
            for(int nt=0;nt<4;nt++){
                mmaf32(accF[mt][nt], aH[mt], bH[nt]);      // hh  (f32 acc)
                mmaf16(accH[mt][nt], aH[mt], bL[nt]);      // hl  (f16 acc)
                mmaf16(accH[mt][nt], aL[mt], bH[nt]);      // lh  (f16 acc, same regs)
            }
        }
        if(i+1<nIter){
            sts_stage(sm+((i+1)&1)*STG, pref, tid);
            __syncthreads();
        }
    }

#pragma unroll
    for(int mt=0;mt<2;mt++)
#pragma unroll
    for(int nt=0;nt<4;nt++){
        int n0=colBase+wn*32+nt*8+((lane&3)<<1);
        float b0=0.f,b1=0.f;
        if(EPI!=3 && bias){ b0=bias[n0]; b1=bias[n0+1]; }
        float l0=0,p30=0,p40=0,p50=0,l1=0,p31=0,p41=0,p51=0;
        if(EPI==3){
            l0=linP[n0]; p30=gpP[n0*6+3]; p40=gpP[n0*6+4]; p50=gpP[n0*6+5];
            l1=linP[n0+1]; p31=gpP[(n0+1)*6+3]; p41=gpP[(n0+1)*6+4]; p51=gpP[(n0+1)*6+5];
        }
#pragma unroll
        for(int hh=0;hh<2;hh++){
            long row=rowBase+wm*32+mt*16+(lane>>2)+hh*8;
            long o=row*(long)N+n0;
            __half2 cr=*(__half2*)&accH[mt][nt][hh];
            float v0=accF[mt][nt][2*hh]  +__low2float(cr) +b0;
            float v1=accF[mt][nt][2*hh+1]+__high2float(cr)+b1;
            if(EPI==1){ v0*=1.f/(1.f+__expf(-v0)); v1*=1.f/(1.f+__expf(-v1)); }
            if(EPI==2){ v0=tanhf(v0); v1=tanhf(v1); }
            if(EPI==3){
                __half2 th=*(const __half2*)(tmphP+o);
                __half2 tl=*(const __half2*)(tmplP+o);
                float t0v=__low2float(th)+__low2float(tl);
                float t1v=__high2float(th)+__high2float(tl);
                float g0=(l0*t0v + 0.5f*sinf(p30*t0v+p40) + 0.5f*cosf(p50*t0v))*0.25f;
                float g1=(l1*t1v + 0.5f*sinf(p31*t1v+p41) + 0.5f*cosf(p51*t1v))*0.25f;
                v0=(t0v + 0.3f*g0 + 0.2f*v0)*(1.0f/1.5f);
                v1=(t1v + 0.3f*g1 + 0.2f*v1)*(1.0f/1.5f);
            }
            if(C32){ float2 f; f.x=v0; f.y=v1; *(float2*)(C32+o)=f; }
            if(Ch){
                fp16 h0,q0,h1,q1; split2(v0,h0,q0); split2(v1,h1,q1);
                __half2 ph=__halves2half2(h0,h1), pl=__halves2half2(q0,q1);
                *(__half2*)(Ch+o)=ph; *(__half2*)(Cl+o)=pl;
            }
        }
    }
}

__global__ void k_init(const float* __restrict__ x,
                       fp16* __restrict__ ch, fp16* __restrict__ cl){
    long idx=(long)blockIdx.x*256+threadIdx.x;
    float v=x[idx];
    fp16 h,l; split2(v,h,l); ch[idx]=h; cl[idx]=l;
}

__device__ __forceinline__ void split_store(const float* W, fp16* oh, fp16* ol,
                                            int K, int N, int do_tanh, long seg, long idx){
    if(idx>=seg) return;
    int k=(int)(idx/N), n=(int)(idx%N);
    float v=W[idx]; if(do_tanh) v=tanhf(v);
    fp16 h,l; split2(v,h,l);
    oh[(long)n*K+k]=h; ol[(long)n*K+k]=l;
}

__global__ void k_split_big(const float* __restrict__ d0w1, const float* __restrict__ d0w2,
                            const float* __restrict__ d1w1, const float* __restrict__ d1w2,
                            fp16* __restrict__ wh, fp16* __restrict__ wl){
    const long O_D0W1=0, O_D0W2=589824, O_D1W1=1179648, O_D1W2=1572864;
    long idx=(long)blockIdx.x*256+threadIdx.x;
    int y=blockIdx.y;
    if(y<3){        long b=(long)y*196608;
        split_store(d0w1+b, wh+O_D0W1+b, wl+O_D0W1+b, 256,768,0,196608,idx);
    } else if(y<6){ long b=(long)(y-3)*196608;
        split_store(d0w2+b, wh+O_D0W2+b, wl+O_D0W2+b, 768,256,0,196608,idx);
    } else if(y<9){ long b=(long)(y-6)*131072;
        split_store(d1w1+b, wh+O_D1W1+b, wl+O_D1W1+b, 256,512,0,131072,idx);
    } else {        long b=(long)(y-9)*131072;
        split_store(d1w2+b, wh+O_D1W2+b, wl+O_D1W2+b, 512,256,0,131072,idx);
    }
}

__global__ void k_split_small(const float* __restrict__ wf, const float* __restrict__ ent,
                              const float* __restrict__ nw1, const float* __restrict__ nw2,
                              fp16* __restrict__ wh, fp16* __restrict__ wl){
    const long O_ATT=1966080, O_TENT=2097152, O_NW1=2621440, O_NW2=2883584;
    long idx=(long)blockIdx.x*256+threadIdx.x;
    int y=blockIdx.y;
    if(y<2){         long b=(long)y*65536;
        split_store(wf+b,  wh+O_ATT+b,  wl+O_ATT+b,  256,256,0,65536,idx);
    } else if(y<10){ long b=(long)(y-2)*65536;
        split_store(ent+b, wh+O_TENT+b, wl+O_TENT+b, 256,256,1,65536,idx);
    } else if(y<14){ long b=(long)(y-10)*65536;
        split_store(nw1+b, wh+O_NW1+b,  wl+O_NW1+b,  256,256,0,65536,idx);
    } else {         long b=(long)(y-14)*65536;
        split_store(nw2+b, wh+O_NW2+b,  wl+O_NW2+b,  256,256,0,65536,idx);
    }
}

__global__ void k_attn_fuse(const float* __restrict__ wqkv, const float* __restrict__ bqkv,
                            const float* __restrict__ wo, const float* __restrict__ bo,
                            float* __restrict__ wf, float* __restrict__ battn){
    int i=blockIdx.y;
    int idx=blockIdx.x*256+threadIdx.x;
    int k=idx>>8, n=idx&255;
    const float* Wv=wqkv+(long)i*256*768+512;
    const float* Wo=wo+(long)i*256*256;
    float s=0.f;
    for(int j=0;j<256;j++) s+=Wv[(long)k*768+j]*Wo[(long)j*256+n];
    wf[(long)i*65536+idx]=s;
    if(k==0){
        float sb=bo[i*256+n];
        for(int j=0;j<256;j++) sb+=bqkv[(long)i*768+512+j]*Wo[(long)j*256+n];
        battn[i*256+n]=sb;
    }
}

__global__ void k_lin(const float* __restrict__ gp, float* __restrict__ lin){
    int idx=blockIdx.x*256+threadIdx.x;
    const float* p=gp+(long)idx*6;
    lin[idx]=sinf(p[0])+cosf(p[1])+tanhf(p[2]);
}

__global__ void k_ln_gelu(const float* __restrict__ h, const float* __restrict__ w, const float* __restrict__ b,
                          fp16* __restrict__ oh, fp16* __restrict__ ol){
    int row=blockIdx.x*8+(threadIdx.x>>5);
    int lane=threadIdx.x&31;
    const float* hr=h+(long)row*768;
    float v[24]; float s=0.f,s2=0.f;
#pragma unroll
    for(int j=0;j<24;j++){ float x=hr[lane+32*j]; v[j]=x; s+=x; s2+=x*x; }
#pragma unroll
    for(int o=16;o;o>>=1){ s+=__shfl_xor_sync(0xffffffffu,s,o); s2+=__shfl_xor_sync(0xffffffffu,s2,o); }
    float mu=s*(1.f/768.f);
    float var=s2*(1.f/768.f)-mu*mu;
    float inv=rsqrtf(var+1e-5f);
    long base=(long)row*768;
#pragma unroll
    for(int j=0;j<24;j++){
        int q=lane+32*j;
        float y=(v[j]-mu)*inv*w[q]+b[q];
        float g=0.5f*y*(1.f+erff(y*0.70710678118654752f));
        fp16 hh,ll; split2(g,hh,ll);
        oh[base+q]=hh; ol[base+q]=ll;
    }
}

__global__ void k_final(const fp16* __restrict__ c2h, const fp16* __restrict__ c2l,
                        const float* __restrict__ nl,
                        fp16* __restrict__ ch, fp16* __restrict__ cl,
                        float* __restrict__ outp, float alpha){
    int row=blockIdx.x*8+(threadIdx.x>>5);
    int lane=threadIdx.x&31;
    long base=(long)row*QD;
    float v[8]; float ss=0.f;
#pragma unroll
    for(int j=0;j<8;j++){
        int q=lane+32*j;
        float x=__half2float(c2h[base+q])+__half2float(c2l[base+q]);
        if(nl) x+=0.1f*nl[base+q];
        float res=__half2float(ch[base+q])+__half2float(cl[base+q]);
        float y=alpha*x+(1.f-alpha)*res;
        v[j]=y; ss+=y*y;
    }
#pragma unroll
    for(int o=16;o;o>>=1) ss+=__shfl_xor_sync(0xffffffffu,ss,o);
    float inv=1.f/(sqrtf(ss)+1e-8f);
#pragma unroll
    for(int j=0;j<8;j++){
        int q=lane+32*j;
        float y=tanhf(v[j]*inv);
        if(outp) outp[base+q]=y;
        else{ fp16 h,l; split2(y,h,l); ch[base+q]=h; cl[base+q]=l; }
    }
}

static void* symaddr(const void* s){ void* p=nullptr; cudaGetSymbolAddress(&p, s); return p; }

static void gemm(int epi, const fp16* Ah,const fp16* Al,const fp16* Bh,const fp16* Bl,
                 const float* bias, float* C32, fp16* Ch, fp16* Cl,
                 const fp16* tmphP, const fp16* tmplP, const float* gpP, const float* linP,
                 int K,int N){
    dim3 grid(N/128, BATCHN/128);
    if(epi==0)      gemm_k<0><<<grid,512,SM_TOT>>>(Ah,Al,Bh,Bl,bias,C32,Ch,Cl,tmphP,tmplP,gpP,linP,K,N);
    else if(epi==1) gemm_k<1><<<grid,512,SM_TOT>>>(Ah,Al,Bh,Bl,bias,C32,Ch,Cl,tmphP,tmplP,gpP,linP,K,N);
    else if(epi==2) gemm_k<2><<<grid,512,SM_TOT>>>(Ah,Al,Bh,Bl,bias,C32,Ch,Cl,tmphP,tmplP,gpP,linP,K,N);
    else            gemm_k<3><<<grid,512,SM_TOT>>>(Ah,Al,Bh,Bl,bias,C32,Ch,Cl,tmphP,tmplP,gpP,linP,K,N);
}

extern "C" void kernel_launch(void* const* d_in, const int* in_sizes, int n_in,
                              void* d_out, int out_size){
    (void)in_sizes;(void)n_in;(void)out_size;
    cudaFuncSetAttribute(gemm_k<0>, cudaFuncAttributeMaxDynamicSharedMemorySize, SM_TOT);
    cudaFuncSetAttribute(gemm_k<1>, cudaFuncAttributeMaxDynamicSharedMemorySize, SM_TOT);
    cudaFuncSetAttribute(gemm_k<2>, cudaFuncAttributeMaxDynamicSharedMemorySize, SM_TOT);
    cudaFuncSetAttribute(gemm_k<3>, cudaFuncAttributeMaxDynamicSharedMemorySize, SM_TOT);

    const float* x   =(const float*)d_in[0];
    const float* d0w1=(const float*)d_in[1];
    const float* d0b1=(const float*)d_in[2];
    const float* lnw =(const float*)d_in[3];
    const float* lnb =(const float*)d_in[4];
    const float* d0w2=(const float*)d_in[5];
    const float* d0b2=(const float*)d_in[6];
    const float* d1w1=(const float*)d_in[7];
    const float* d1b1=(const float*)d_in[8];
    const float* d1w2=(const float*)d_in[9];
    const float* d1b2=(const float*)d_in[10];
    const float* wqkv=(const float*)d_in[11];
    const float* bqkv=(const float*)d_in[12];
    const float* wo  =(const float*)d_in[13];
    const float* bo  =(const float*)d_in[14];
    const float* gp  =(const float*)d_in[15];
    const float* ent =(const float*)d_in[16];
    const float* nw1 =(const float*)d_in[17];
    const float* nb1 =(const float*)d_in[18];
    const float* nw2 =(const float*)d_in[19];
    const float* nb2 =(const float*)d_in[20];

    float* h32  =(float*)symaddr(g_h32);
    float* nl32 =(float*)symaddr(g_nl32);
    fp16* curh=(fp16*)symaddr(g_curh); fp16* curl=(fp16*)symaddr(g_curl);
    fp16* hh_ =(fp16*)symaddr(g_hh);   fp16* hl_ =(fp16*)symaddr(g_hl);
    fp16* tmph=(fp16*)symaddr(g_tmph); fp16* tmpl=(fp16*)symaddr(g_tmpl);
    fp16* c2h =(fp16*)symaddr(g_c2h);  fp16* c2l =(fp16*)symaddr(g_c2l);
    fp16* wh  =(fp16*)symaddr(g_w_h);  fp16* wl  =(fp16*)symaddr(g_w_l);
    float* wf   =(float*)symaddr(g_wf);
    float* battn=(float*)symaddr(g_battn);
    float* lin  =(float*)symaddr(g_lin);

    const long O_D0W1=0, O_D0W2=589824, O_D1W1=1179648, O_D1W2=1572864;
    const long O_ATT=1966080, O_TENT=2097152, O_NW1=2621440, O_NW2=2883584;

    // launches 1-3 prep; #4 = first main GEMM (ncu profiles #4)
    k_split_big <<<dim3(768,12),256>>>(d0w1,d0w2,d1w1,d1w2, wh,wl);
    k_init<<<BATCHN*QD/256,256>>>(x, curh, curl);
    k_attn_fuse <<<dim3(256,2),256>>>(wqkv,bqkv,wo,bo,wf,battn);

    for(int li=0;li<8;li++){
        int t=li%3;
        if(t==0){
            int i=li/3;
            gemm(0, curh,curl, wh+O_D0W1+(long)i*196608, wl+O_D0W1+(long)i*196608,
                 d0b1+(long)i*768, h32, nullptr,nullptr, nullptr,nullptr,nullptr,nullptr, 256,768);
            if(li==0){
                k_split_small<<<dim3(256,18),256>>>(wf,ent,nw1,nw2, wh,wl);
                k_lin<<<8,256>>>(gp, lin);
            }
            k_ln_gelu<<<BATCHN/8,256>>>(h32, lnw+(long)i*768, lnb+(long)i*768, hh_, hl_);
            gemm(0, hh_,hl_, wh+O_D0W2+(long)i*196608, wl+O_D0W2+(long)i*196608,
                 d0b2+(long)i*256, nullptr, tmph,tmpl, nullptr,nullptr,nullptr,nullptr, 768,256);
        } else if(t==1){
            int i=(li-1)/3;
            gemm(1, curh,curl, wh+O_D1W1+(long)i*131072, wl+O_D1W1+(long)i*131072,
                 d1b1+(long)i*512, nullptr, hh_,hl_, nullptr,nullptr,nullptr,nullptr, 256,512);
            gemm(0, hh_,hl_, wh+O_D1W2+(long)i*131072, wl+O_D1W2+(long)i*131072,
                 d1b2+(long)i*256, nullptr, tmph,tmpl, nullptr,nullptr,nullptr,nullptr, 512,256);
        } else {
            int i=(li-2)/3;
            gemm(0, curh,curl, wh+O_ATT+(long)i*65536, wl+O_ATT+(long)i*65536,
                 battn+(long)i*256, nullptr, tmph,tmpl, nullptr,nullptr,nullptr,nullptr, 256,256);
        }
        gemm(3, tmph,tmpl, wh+O_TENT+(long)li*65536, wl+O_TENT+(long)li*65536,
             nullptr, nullptr, c2h,c2l, tmph,tmpl, gp+(long)li*256*6, lin+(long)li*256, 256,256);

        const float* nlptr=nullptr;
        if(li&1){
            int j=li/2;
            gemm(2, c2h,c2l, wh+O_NW1+(long)j*65536, wl+O_NW1+(long)j*65536,
                 nb1+(long)j*256, nullptr, hh_,hl_, nullptr,nullptr,nullptr,nullptr, 256,256);
            gemm(0, hh_,hl_, wh+O_NW2+(long)j*65536, wl+O_NW2+(long)j*65536,
                 nb2+(long)j*256, nl32, nullptr,nullptr, nullptr,nullptr,nullptr,nullptr, 256,256);
            nlptr=nl32;
        }
        float alpha=(li<4)?0.8f:0.6f;
        float* outp=(li==7)?(float*)d_out:nullptr;
        k_final<<<BATCHN/8,256>>>(c2h,c2l, nlptr, curh, curl, outp, alpha);
    }
}